// round 3
// baseline (speedup 1.0000x reference)
#include <cuda_runtime.h>
#include <math.h>

#define NN 131072
#define EE 1048576

// ---------------- scratch (device globals; no allocation allowed) ----------------
__device__ int   g_deg[NN];
__device__ int   g_rowptr[NN + 1];
__device__ int   g_cursor[NN];
__device__ int   g_csr[EE];
__device__ float g_embW1[5 * 256];
__device__ float g_tas[20];
__device__ float g_tad[20];
__device__ float g_bufA[(size_t)NN * 256];   // layer inputs x2 / x3
__device__ float g_bufB[(size_t)NN * 256];   // GEMM2 output h2
__device__ float g_h3[(size_t)NN * 64];      // GEMM3 output
__device__ float g_x4[(size_t)NN * 64];      // layer3 output (pre-fc)
__device__ float g_as[NN * 4];
__device__ float g_ad[NN * 4];

// ---------------- helpers ----------------
__device__ __forceinline__ float lrelu(float e) { return fmaxf(e, 0.2f * e); }
__device__ __forceinline__ float elu(float v)   { return v > 0.f ? v : expm1f(v); }
__device__ __forceinline__ float sel4(float a, float b, float c, float d, int i) {
    float lo = (i & 1) ? b : a;
    float hi = (i & 1) ? d : c;
    return (i & 2) ? hi : lo;
}

// ---------------- CSR build ----------------
__global__ void k_zero_deg() {
    int i = blockIdx.x * blockDim.x + threadIdx.x;
    if (i < NN) g_deg[i] = 0;
}

__global__ void k_hist(const int* __restrict__ dst) {
    int i = blockIdx.x * blockDim.x + threadIdx.x;
    if (i < EE) atomicAdd(&g_deg[dst[i]], 1);
}

__global__ void k_scan() {
    __shared__ int sm[1024];
    int t = threadIdx.x;
    int base = t * 128;
    int s = 0;
#pragma unroll 4
    for (int j = 0; j < 128; j++) s += g_deg[base + j];
    sm[t] = s;
    __syncthreads();
    for (int off = 1; off < 1024; off <<= 1) {
        int v = (t >= off) ? sm[t - off] : 0;
        __syncthreads();
        sm[t] += v;
        __syncthreads();
    }
    int run = sm[t] - s;  // exclusive prefix
    for (int j = 0; j < 128; j++) {
        int d = g_deg[base + j];
        g_rowptr[base + j] = run;
        g_cursor[base + j] = run;
        run += d;
    }
    if (t == 1023) g_rowptr[NN] = run;
}

__global__ void k_scatter(const int* __restrict__ src, const int* __restrict__ dst) {
    int i = blockIdx.x * blockDim.x + threadIdx.x;
    if (i < EE) {
        int p = atomicAdd(&g_cursor[dst[i]], 1);
        g_csr[p] = src[i];
    }
}

// ---------------- layer-1 collapse: embW1 = emb @ W1 (5x256), logit tables ----------------
__global__ void k_prep1(const float* __restrict__ emb, const float* __restrict__ W1,
                        const float* __restrict__ a1s, const float* __restrict__ a1d) {
    int t = threadIdx.x;  // 256 threads
    for (int v = 0; v < 5; v++) {
        float s = 0.f;
        for (int k = 0; k < 64; k++) s += emb[v * 64 + k] * W1[k * 256 + t];
        g_embW1[v * 256 + t] = s;
    }
    __syncthreads();
    if (t < 20) {
        int v = t >> 2, h = t & 3;
        float sa = 0.f, sd = 0.f;
        for (int c = 0; c < 64; c++) {
            float hv = g_embW1[v * 256 + h * 64 + c];
            sa += hv * a1s[h * 64 + c];
            sd += hv * a1d[h * 64 + c];
        }
        g_tas[t] = sa;
        g_tad[t] = sd;
    }
}

// ---------------- layer 1 aggregation (table-based, warp per node) ----------------
__global__ void __launch_bounds__(256) k_agg1(const int* __restrict__ x,
                                              const float* __restrict__ bias) {
    __shared__ float s_emb[5 * 256];
    __shared__ float s_tas[20], s_tad[20];
    int tid = threadIdx.x;
    for (int i = tid; i < 5 * 256; i += 256) s_emb[i] = g_embW1[i];
    if (tid < 20) { s_tas[tid] = g_tas[tid]; s_tad[tid] = g_tad[tid]; }
    __syncthreads();

    int n = (blockIdx.x * 256 + tid) >> 5;
    int lane = tid & 31;
    int xn = x[n];
    int start = g_rowptr[n];
    int deg = g_rowptr[n + 1] - start;

    float ad0 = s_tad[xn * 4 + 0], ad1 = s_tad[xn * 4 + 1];
    float ad2 = s_tad[xn * 4 + 2], ad3 = s_tad[xn * 4 + 3];
    float as0 = s_tas[xn * 4 + 0], as1 = s_tas[xn * 4 + 1];
    float as2 = s_tas[xn * 4 + 2], as3 = s_tas[xn * 4 + 3];

    float m0 = lrelu(as0 + ad0), m1 = lrelu(as1 + ad1);
    float m2 = lrelu(as2 + ad2), m3 = lrelu(as3 + ad3);
    int xs0 = 0, xs1 = 0;
    for (int i = lane; i < deg; i += 32) {
        int s = g_csr[start + i];
        int xv = x[s];
        if (i < 32) xs0 = xv; else if (i < 64) xs1 = xv;
        m0 = fmaxf(m0, lrelu(s_tas[xv * 4 + 0] + ad0));
        m1 = fmaxf(m1, lrelu(s_tas[xv * 4 + 1] + ad1));
        m2 = fmaxf(m2, lrelu(s_tas[xv * 4 + 2] + ad2));
        m3 = fmaxf(m3, lrelu(s_tas[xv * 4 + 3] + ad3));
    }
#pragma unroll
    for (int off = 16; off; off >>= 1) {
        m0 = fmaxf(m0, __shfl_xor_sync(0xffffffffu, m0, off));
        m1 = fmaxf(m1, __shfl_xor_sync(0xffffffffu, m1, off));
        m2 = fmaxf(m2, __shfl_xor_sync(0xffffffffu, m2, off));
        m3 = fmaxf(m3, __shfl_xor_sync(0xffffffffu, m3, off));
    }
    int myh = lane >> 3;
    float mh  = sel4(m0, m1, m2, m3, myh);
    float adh = sel4(ad0, ad1, ad2, ad3, myh);
    float ash = sel4(as0, as1, as2, as3, myh);

    float a0, a1, a2, a3, a4, a5, a6, a7, dloc;
    {   // self-loop
        float w = __expf(lrelu(ash + adh) - mh);
        dloc = w;
        const float4* p = (const float4*)(s_emb + xn * 256 + lane * 8);
        float4 v0 = p[0], v1 = p[1];
        a0 = w * v0.x; a1 = w * v0.y; a2 = w * v0.z; a3 = w * v0.w;
        a4 = w * v1.x; a5 = w * v1.y; a6 = w * v1.z; a7 = w * v1.w;
    }
    for (int i = 0; i < deg; i++) {
        int xv;
        if (i < 32)       xv = __shfl_sync(0xffffffffu, xs0, i);
        else if (i < 64)  xv = __shfl_sync(0xffffffffu, xs1, i & 31);
        else              xv = x[g_csr[start + i]];
        float e = lrelu(s_tas[xv * 4 + myh] + adh);
        float w = __expf(e - mh);
        dloc += w;
        const float4* p = (const float4*)(s_emb + xv * 256 + lane * 8);
        float4 v0 = p[0], v1 = p[1];
        a0 += w * v0.x; a1 += w * v0.y; a2 += w * v0.z; a3 += w * v0.w;
        a4 += w * v1.x; a5 += w * v1.y; a6 += w * v1.z; a7 += w * v1.w;
    }
    float inv = 1.f / (dloc + 1e-16f);
    int c = lane * 8;
    float4 b0 = *(const float4*)(bias + c);
    float4 b1v = *(const float4*)(bias + c + 4);
    float4 o0, o1;
    o0.x = elu(a0 * inv + b0.x);  o0.y = elu(a1 * inv + b0.y);
    o0.z = elu(a2 * inv + b0.z);  o0.w = elu(a3 * inv + b0.w);
    o1.x = elu(a4 * inv + b1v.x); o1.y = elu(a5 * inv + b1v.y);
    o1.z = elu(a6 * inv + b1v.z); o1.w = elu(a7 * inv + b1v.w);
    *(float4*)(g_bufA + (size_t)n * 256 + c)     = o0;
    *(float4*)(g_bufA + (size_t)n * 256 + c + 4) = o1;
}

// ---------------- SGEMM: C[M,Ncols] = A[M,K] @ B[K,Ncols]; BM=128 BN=64 BK=8 ----------------
__global__ void __launch_bounds__(256) k_sgemm(const float* __restrict__ A,
                                               const float* __restrict__ B,
                                               float* __restrict__ C,
                                               int K, int Ncols) {
    __shared__ float As[8][128];
    __shared__ float Bs[8][64];
    int m0 = blockIdx.y * 128, n0 = blockIdx.x * 64;
    int tid = threadIdx.x;
    int tx = tid & 15, ty = tid >> 4;
    float acc[8][4] = {};
    for (int k0 = 0; k0 < K; k0 += 8) {
        {
            int r = tid >> 1, c = (tid & 1) * 4;
            float4 va = *(const float4*)(A + (size_t)(m0 + r) * K + k0 + c);
            As[c + 0][r] = va.x; As[c + 1][r] = va.y;
            As[c + 2][r] = va.z; As[c + 3][r] = va.w;
        }
        if (tid < 128) {
            int rb = tid >> 4, cb = (tid & 15) * 4;
            *(float4*)&Bs[rb][cb] = *(const float4*)(B + (size_t)(k0 + rb) * Ncols + n0 + cb);
        }
        __syncthreads();
#pragma unroll
        for (int kk = 0; kk < 8; kk++) {
            float a[8], b[4];
            *(float4*)a       = *(const float4*)&As[kk][ty * 8];
            *(float4*)(a + 4) = *(const float4*)&As[kk][ty * 8 + 4];
            *(float4*)b       = *(const float4*)&Bs[kk][tx * 4];
#pragma unroll
            for (int i = 0; i < 8; i++)
#pragma unroll
                for (int j = 0; j < 4; j++) acc[i][j] += a[i] * b[j];
        }
        __syncthreads();
    }
#pragma unroll
    for (int i = 0; i < 8; i++) {
        float4 v = {acc[i][0], acc[i][1], acc[i][2], acc[i][3]};
        *(float4*)(C + (size_t)(m0 + ty * 8 + i) * Ncols + n0 + tx * 4) = v;
    }
}

// ---------------- attention logits: alpha_s/alpha_d per node ----------------
__global__ void __launch_bounds__(256) k_alpha4(const float* __restrict__ feat,
                                                const float* __restrict__ asrc,
                                                const float* __restrict__ adst) {
    int n = (blockIdx.x * 256 + threadIdx.x) >> 5;
    int lane = threadIdx.x & 31;
    const float* fr = feat + (size_t)n * 256;
#pragma unroll
    for (int h = 0; h < 4; h++) {
        float x0 = fr[h * 64 + lane], x1 = fr[h * 64 + 32 + lane];
        float p = x0 * asrc[h * 64 + lane] + x1 * asrc[h * 64 + 32 + lane];
        float q = x0 * adst[h * 64 + lane] + x1 * adst[h * 64 + 32 + lane];
#pragma unroll
        for (int off = 16; off; off >>= 1) {
            p += __shfl_xor_sync(0xffffffffu, p, off);
            q += __shfl_xor_sync(0xffffffffu, q, off);
        }
        if (lane == 0) { g_as[n * 4 + h] = p; g_ad[n * 4 + h] = q; }
    }
}

__global__ void __launch_bounds__(256) k_alpha1(const float* __restrict__ feat,
                                                const float* __restrict__ asrc,
                                                const float* __restrict__ adst) {
    int n = (blockIdx.x * 256 + threadIdx.x) >> 5;
    int lane = threadIdx.x & 31;
    const float* fr = feat + (size_t)n * 64;
    float x0 = fr[lane], x1 = fr[32 + lane];
    float p = x0 * asrc[lane] + x1 * asrc[32 + lane];
    float q = x0 * adst[lane] + x1 * adst[32 + lane];
#pragma unroll
    for (int off = 16; off; off >>= 1) {
        p += __shfl_xor_sync(0xffffffffu, p, off);
        q += __shfl_xor_sync(0xffffffffu, q, off);
    }
    if (lane == 0) { g_as[n] = p; g_ad[n] = q; }
}

// ---------------- layer 2 aggregation (H=4, 256 ch, warp per node) ----------------
__global__ void __launch_bounds__(256) k_agg4(const float* __restrict__ feat,
                                              const float* __restrict__ bias,
                                              float* __restrict__ out) {
    int tid = threadIdx.x;
    int n = (blockIdx.x * 256 + tid) >> 5;
    int lane = tid & 31;
    int start = g_rowptr[n];
    int deg = g_rowptr[n + 1] - start;
    float4 adv = *(const float4*)(g_ad + n * 4);
    float4 asv = *(const float4*)(g_as + n * 4);
    float m0 = lrelu(asv.x + adv.x), m1 = lrelu(asv.y + adv.y);
    float m2 = lrelu(asv.z + adv.z), m3 = lrelu(asv.w + adv.w);
    int s0 = 0, s1 = 0;
    for (int i = lane; i < deg; i += 32) {
        int s = g_csr[start + i];
        if (i < 32) s0 = s; else if (i < 64) s1 = s;
        float4 av = *(const float4*)(g_as + s * 4);
        m0 = fmaxf(m0, lrelu(av.x + adv.x));
        m1 = fmaxf(m1, lrelu(av.y + adv.y));
        m2 = fmaxf(m2, lrelu(av.z + adv.z));
        m3 = fmaxf(m3, lrelu(av.w + adv.w));
    }
#pragma unroll
    for (int off = 16; off; off >>= 1) {
        m0 = fmaxf(m0, __shfl_xor_sync(0xffffffffu, m0, off));
        m1 = fmaxf(m1, __shfl_xor_sync(0xffffffffu, m1, off));
        m2 = fmaxf(m2, __shfl_xor_sync(0xffffffffu, m2, off));
        m3 = fmaxf(m3, __shfl_xor_sync(0xffffffffu, m3, off));
    }
    int myh = lane >> 3;
    float mh  = sel4(m0, m1, m2, m3, myh);
    float adh = sel4(adv.x, adv.y, adv.z, adv.w, myh);
    float ash = sel4(asv.x, asv.y, asv.z, asv.w, myh);

    float a0, a1, a2, a3, a4, a5, a6, a7, dloc;
    {
        float w = __expf(lrelu(ash + adh) - mh);
        dloc = w;
        const float4* p = (const float4*)(feat + (size_t)n * 256 + lane * 8);
        float4 v0 = p[0], v1 = p[1];
        a0 = w * v0.x; a1 = w * v0.y; a2 = w * v0.z; a3 = w * v0.w;
        a4 = w * v1.x; a5 = w * v1.y; a6 = w * v1.z; a7 = w * v1.w;
    }
    for (int i = 0; i < deg; i++) {
        int s;
        if (i < 32)      s = __shfl_sync(0xffffffffu, s0, i);
        else if (i < 64) s = __shfl_sync(0xffffffffu, s1, i & 31);
        else             s = g_csr[start + i];
        float e = lrelu(g_as[s * 4 + myh] + adh);
        float w = __expf(e - mh);
        dloc += w;
        const float4* p = (const float4*)(feat + (size_t)s * 256 + lane * 8);
        float4 v0 = p[0], v1 = p[1];
        a0 += w * v0.x; a1 += w * v0.y; a2 += w * v0.z; a3 += w * v0.w;
        a4 += w * v1.x; a5 += w * v1.y; a6 += w * v1.z; a7 += w * v1.w;
    }
    float inv = 1.f / (dloc + 1e-16f);
    int c = lane * 8;
    float4 b0 = *(const float4*)(bias + c);
    float4 b1v = *(const float4*)(bias + c + 4);
    float4 o0, o1;
    o0.x = elu(a0 * inv + b0.x);  o0.y = elu(a1 * inv + b0.y);
    o0.z = elu(a2 * inv + b0.z);  o0.w = elu(a3 * inv + b0.w);
    o1.x = elu(a4 * inv + b1v.x); o1.y = elu(a5 * inv + b1v.y);
    o1.z = elu(a6 * inv + b1v.z); o1.w = elu(a7 * inv + b1v.w);
    *(float4*)(out + (size_t)n * 256 + c)     = o0;
    *(float4*)(out + (size_t)n * 256 + c + 4) = o1;
}

// ---------------- layer 3 aggregation (H=1, 64 ch, warp per node) ----------------
__global__ void __launch_bounds__(256) k_agg_h1(const float* __restrict__ feat,
                                                const float* __restrict__ bias,
                                                float* __restrict__ out) {
    int tid = threadIdx.x;
    int n = (blockIdx.x * 256 + tid) >> 5;
    int lane = tid & 31;
    int start = g_rowptr[n];
    int deg = g_rowptr[n + 1] - start;
    float adn = g_ad[n];
    float asn = g_as[n];
    float m = lrelu(asn + adn);
    int s0 = 0, s1 = 0;
    for (int i = lane; i < deg; i += 32) {
        int s = g_csr[start + i];
        if (i < 32) s0 = s; else if (i < 64) s1 = s;
        m = fmaxf(m, lrelu(g_as[s] + adn));
    }
#pragma unroll
    for (int off = 16; off; off >>= 1)
        m = fmaxf(m, __shfl_xor_sync(0xffffffffu, m, off));

    float a0, a1, dloc;
    {
        float w = __expf(lrelu(asn + adn) - m);
        dloc = w;
        float2 v = *(const float2*)(feat + (size_t)n * 64 + lane * 2);
        a0 = w * v.x; a1 = w * v.y;
    }
    for (int i = 0; i < deg; i++) {
        int s;
        if (i < 32)      s = __shfl_sync(0xffffffffu, s0, i);
        else if (i < 64) s = __shfl_sync(0xffffffffu, s1, i & 31);
        else             s = g_csr[start + i];
        float w = __expf(lrelu(g_as[s] + adn) - m);
        dloc += w;
        float2 v = *(const float2*)(feat + (size_t)s * 64 + lane * 2);
        a0 += w * v.x; a1 += w * v.y;
    }
    float inv = 1.f / (dloc + 1e-16f);
    int c = lane * 2;
    float2 o;
    o.x = elu(a0 * inv + bias[c]);
    o.y = elu(a1 * inv + bias[c + 1]);
    *(float2*)(out + (size_t)n * 64 + c) = o;
}

// ---------------- final fc: out[n,5] = x4[n,:] @ fc_w + fc_b ----------------
__global__ void __launch_bounds__(256) k_fc(const float* __restrict__ x4,
                                            const float* __restrict__ fcw,
                                            const float* __restrict__ fcb,
                                            float* __restrict__ out) {
    int n = (blockIdx.x * 256 + threadIdx.x) >> 5;
    int lane = threadIdx.x & 31;
    float f0 = x4[(size_t)n * 64 + lane];
    float f1 = x4[(size_t)n * 64 + 32 + lane];
#pragma unroll
    for (int j = 0; j < 5; j++) {
        float p = f0 * fcw[lane * 5 + j] + f1 * fcw[(lane + 32) * 5 + j];
#pragma unroll
        for (int off = 16; off; off >>= 1)
            p += __shfl_xor_sync(0xffffffffu, p, off);
        if (lane == 0) out[(size_t)n * 5 + j] = p + fcb[j];
    }
}

// ---------------- launcher ----------------
extern "C" void kernel_launch(void* const* d_in, const int* in_sizes, int n_in,
                              void* d_out, int out_size) {
    const int*   x    = (const int*)d_in[0];
    const int*   ei   = (const int*)d_in[1];
    const float* emb  = (const float*)d_in[2];
    const float* W1   = (const float*)d_in[3];
    const float* a1s  = (const float*)d_in[4];
    const float* a1d  = (const float*)d_in[5];
    const float* b1   = (const float*)d_in[6];
    const float* W2   = (const float*)d_in[7];
    const float* a2s  = (const float*)d_in[8];
    const float* a2d  = (const float*)d_in[9];
    const float* b2   = (const float*)d_in[10];
    const float* W3   = (const float*)d_in[11];
    const float* a3s  = (const float*)d_in[12];
    const float* a3d  = (const float*)d_in[13];
    const float* b3   = (const float*)d_in[14];
    const float* fcw  = (const float*)d_in[15];
    const float* fcb  = (const float*)d_in[16];
    float* out = (float*)d_out;

    void *pA, *pB, *pH3, *pX4;
    cudaGetSymbolAddress(&pA, g_bufA);
    cudaGetSymbolAddress(&pB, g_bufB);
    cudaGetSymbolAddress(&pH3, g_h3);
    cudaGetSymbolAddress(&pX4, g_x4);
    float* bufA = (float*)pA;
    float* bufB = (float*)pB;
    float* h3   = (float*)pH3;
    float* x4v  = (float*)pX4;

    const int* src = ei;
    const int* dst = ei + EE;

    // CSR build (per call; deterministic up to fp-harmless ordering)
    k_zero_deg<<<NN / 256, 256>>>();
    k_hist<<<EE / 256, 256>>>(dst);
    k_scan<<<1, 1024>>>();
    k_scatter<<<EE / 256, 256>>>(src, dst);

    // layer 1 (collapsed to 5-row tables)
    k_prep1<<<1, 256>>>(emb, W1, a1s, a1d);
    k_agg1<<<NN / 8, 256>>>(x, b1);                    // -> bufA = x2 [N,256]

    // layer 2
    k_sgemm<<<dim3(256 / 64, NN / 128), 256>>>(bufA, W2, bufB, 256, 256);
    k_alpha4<<<NN / 8, 256>>>(bufB, a2s, a2d);
    k_agg4<<<NN / 8, 256>>>(bufB, b2, bufA);           // -> bufA = x3 [N,256]

    // layer 3
    k_sgemm<<<dim3(64 / 64, NN / 128), 256>>>(bufA, W3, h3, 256, 64);
    k_alpha1<<<NN / 8, 256>>>(h3, a3s, a3d);
    k_agg_h1<<<NN / 8, 256>>>(h3, b3, x4v);            // -> x4 [N,64]

    // fc
    k_fc<<<NN / 8, 256>>>(x4v, fcw, fcb, out);
}